// round 6
// baseline (speedup 1.0000x reference)
#include <cuda_runtime.h>
#include <math.h>

#define NN   100000
#define EE   3200000
#define INC  256
#define HIDC 32
#define OUTC 64
#define NPAD 102400   // NN padded to multiple of 4096 for the scan

// ---------------- device scratch (no allocations allowed) ----------------
__device__ __align__(16) int   g_src[EE];
__device__ __align__(16) int   g_dst[EE];
__device__ __align__(16) int   g_csr[EE];
__device__ __align__(16) int   g_rowptr[NPAD + 8];
__device__ __align__(16) int   g_cursor[NN];
__device__ __align__(16) int   g_degi[NPAD];
__device__ __align__(16) float g_dinv[NN];
__device__ __align__(16) int   g_bsum[32];
__device__ int   g_is64;
__device__ __align__(16) float g_h1[NN * HIDC];   // x@w1, pre-scaled by dinv[row]
__device__ __align__(16) float g_o1[NN * HIDC];   // relu(layer1 output)
__device__ __align__(16) float g_h2[NN * OUTC];   // o1@w2, pre-scaled by dinv[row]

// ---------------- -1: detect edge dtype (int32 vs int64) ----------------
// If int64 (values < 2^31), every odd 32-bit word of the payload is zero.
__global__ void k_detect(const int* __restrict__ w) {
    __shared__ int any;
    if (threadIdx.x == 0) any = 0;
    __syncthreads();
    int v = w[2 * threadIdx.x + 1];          // odd words of first 512 ints
    if (v != 0) atomicOr(&any, 1);
    __syncthreads();
    if (threadIdx.x == 0) g_is64 = (any == 0) ? 1 : 0;
}

// ---------------- 0: zero degree counters ----------------
__global__ void k_zero() {
    int i = blockIdx.x * 256 + threadIdx.x;
    if (i < NPAD) g_degi[i] = 0;
    if (i < 32)   g_bsum[i] = 0;
}

// ---------------- 1: decode edges, count in-degree ----------------
__global__ void k_cast(const int* __restrict__ ei) {
    int e = blockIdx.x * 256 + threadIdx.x;
    if (e < EE) {
        int s, d;
        if (g_is64) {                       // int64 little-endian: take low words
            s = ei[2 * (size_t)e];
            d = ei[2 * ((size_t)EE + e)];
        } else {                            // int32 layout [2, E]
            s = ei[e];
            d = ei[EE + e];
        }
        s = min(max(s, 0), NN - 1);
        d = min(max(d, 0), NN - 1);
        g_src[e] = s;
        g_dst[e] = d;
        atomicAdd(&g_degi[d], 1);
    }
}

// ---------------- 2a: per-block exclusive scan (4096 items/block, 512 thr) ----------------
__global__ void k_scan1() {
    __shared__ int wsum[32];
    int tid = threadIdx.x, lane = tid & 31, w = tid >> 5;
    int base = blockIdx.x * 4096 + tid * 8;
    int4 a = *(const int4*)&g_degi[base];
    int4 b = *(const int4*)&g_degi[base + 4];
    int p0 = a.x;
    int p1 = p0 + a.y;
    int p2 = p1 + a.z;
    int p3 = p2 + a.w;
    int p4 = p3 + b.x;
    int p5 = p4 + b.y;
    int p6 = p5 + b.z;
    int p7 = p6 + b.w;      // inclusive within thread
    int tot = p7;
    int x = tot;
    #pragma unroll
    for (int off = 1; off < 32; off <<= 1) {
        int y = __shfl_up_sync(0xffffffffu, x, off);
        if (lane >= off) x += y;
    }
    if (lane == 31) wsum[w] = x;   // warp total (inclusive across warps)
    int texcl = x - tot;           // exclusive offset of this thread within warp
    __syncthreads();
    if (w == 0) {
        int v = (lane < 16) ? wsum[lane] : 0;
        int xx = v;
        #pragma unroll
        for (int off = 1; off < 32; off <<= 1) {
            int y = __shfl_up_sync(0xffffffffu, xx, off);
            if (lane >= off) xx += y;
        }
        if (lane == 15) g_bsum[blockIdx.x] = xx;   // block total
        wsum[lane] = xx - v;                        // exclusive warp offsets
    }
    __syncthreads();
    int off0 = wsum[w] + texcl;
    int4 r0 = make_int4(off0, off0 + p0, off0 + p1, off0 + p2);
    int4 r1 = make_int4(off0 + p3, off0 + p4, off0 + p5, off0 + p6);
    *(int4*)&g_rowptr[base]     = r0;
    *(int4*)&g_rowptr[base + 4] = r1;
}

// ---------------- 2b: scan the 25 block sums ----------------
__global__ void k_scan2() {
    int lane = threadIdx.x;
    int v = g_bsum[lane];
    int x = v;
    #pragma unroll
    for (int off = 1; off < 32; off <<= 1) {
        int y = __shfl_up_sync(0xffffffffu, x, off);
        if (lane >= off) x += y;
    }
    g_bsum[lane] = x - v;   // exclusive
}

// ---------------- 2c: add block offsets, init cursor, compute dinv ----------------
__global__ void k_scan3() {
    int i = blockIdx.x * 256 + threadIdx.x;
    if (i < NN) {
        int r = g_rowptr[i] + g_bsum[i >> 12];
        g_rowptr[i] = r;
        g_cursor[i] = r;
        float dg = (float)g_degi[i];
        g_dinv[i] = (dg > 0.0f) ? rsqrtf(dg) : 0.0f;
    }
    if (i == 0) g_rowptr[NN] = EE;
}

// ---------------- 3: scatter edges into CSR slots ----------------
__global__ void k_scatter() {
    int e = blockIdx.x * 256 + threadIdx.x;
    if (e < EE) {
        int d = g_dst[e];
        int p = atomicAdd(&g_cursor[d], 1);
        g_csr[p] = g_src[e];
    }
}

// ---------------- 4: GEMM1  h1 = (x @ w1) * dinv[row] ----------------
// 256 threads (8 warps), 16 rows/block, 2 rows/warp, col = lane.
// Static shared: ws 32KB + xs 16KB = 48KB.
__global__ void k_gemm1(const float* __restrict__ x, const float* __restrict__ w) {
    __shared__ float ws[INC * HIDC];   // [256][32]  32 KB
    __shared__ float xs[16 * INC];     // [16][256]  16 KB
    int tid = threadIdx.x;

    const float4* wg = (const float4*)w;
    float4* ws4 = (float4*)ws;
    #pragma unroll
    for (int i = 0; i < 8; i++) ws4[tid + i * 256] = wg[tid + i * 256];

    const float4* xg = (const float4*)(x + (size_t)blockIdx.x * 16 * INC);
    float4* xs4 = (float4*)xs;
    #pragma unroll
    for (int i = 0; i < 4; i++) xs4[tid + i * 256] = xg[tid + i * 256];
    __syncthreads();

    int wp = tid >> 5, lane = tid & 31;
    const float* xp = xs + (wp * 2) * INC;
    float acc0 = 0.f, acc1 = 0.f;
    #pragma unroll 8
    for (int k = 0; k < INC; k += 4) {
        float4 a0 = *(const float4*)(xp + k);
        float4 a1 = *(const float4*)(xp + INC + k);
        float b0 = ws[(k + 0) * HIDC + lane];
        float b1 = ws[(k + 1) * HIDC + lane];
        float b2 = ws[(k + 2) * HIDC + lane];
        float b3 = ws[(k + 3) * HIDC + lane];
        acc0 = fmaf(a0.x, b0, acc0); acc0 = fmaf(a0.y, b1, acc0);
        acc0 = fmaf(a0.z, b2, acc0); acc0 = fmaf(a0.w, b3, acc0);
        acc1 = fmaf(a1.x, b0, acc1); acc1 = fmaf(a1.y, b1, acc1);
        acc1 = fmaf(a1.z, b2, acc1); acc1 = fmaf(a1.w, b3, acc1);
    }
    int row = blockIdx.x * 16 + wp * 2;
    float d0 = g_dinv[row], d1 = g_dinv[row + 1];
    g_h1[(row + 0) * HIDC + lane] = acc0 * d0;
    g_h1[(row + 1) * HIDC + lane] = acc1 * d1;
}

// ---------------- 5: aggregation layer 1, warp per node, col = lane ----------------
__global__ void k_agg1(const float* __restrict__ b1) {
    int node = blockIdx.x * 8 + (threadIdx.x >> 5);
    int lane = threadIdx.x & 31;
    int s = g_rowptr[node], e = g_rowptr[node + 1];
    float acc = 0.f;
    int i = s;
    for (; i + 4 <= e; i += 4) {
        int i0 = g_csr[i], i1 = g_csr[i + 1], i2 = g_csr[i + 2], i3 = g_csr[i + 3];
        float v0 = __ldg(&g_h1[i0 * HIDC + lane]);
        float v1 = __ldg(&g_h1[i1 * HIDC + lane]);
        float v2 = __ldg(&g_h1[i2 * HIDC + lane]);
        float v3 = __ldg(&g_h1[i3 * HIDC + lane]);
        acc += (v0 + v1) + (v2 + v3);
    }
    for (; i < e; i++) acc += __ldg(&g_h1[g_csr[i] * HIDC + lane]);
    float o = b1[lane] + g_dinv[node] * acc;
    g_o1[node * HIDC + lane] = fmaxf(o, 0.0f);
}

// ---------------- 6: GEMM2  h2 = (o1 @ w2) * dinv[row] ----------------
// 256 threads, 32 rows/block, 4 rows/warp, 2 cols/thread. Static shared 12KB.
__global__ void k_gemm2(const float* __restrict__ w2) {
    __shared__ float ws[HIDC * OUTC];   // 8 KB
    __shared__ float xs[32 * HIDC];     // 4 KB
    int tid = threadIdx.x;
    for (int i = tid; i < HIDC * OUTC; i += 256) ws[i] = w2[i];
    int row0 = blockIdx.x * 32;
    for (int i = tid; i < 32 * HIDC; i += 256) xs[i] = g_o1[row0 * HIDC + i];
    __syncthreads();

    int wp = tid >> 5, lane = tid & 31;
    const float* xp = xs + (wp * 4) * HIDC;
    float2 acc0 = {0.f, 0.f}, acc1 = {0.f, 0.f}, acc2 = {0.f, 0.f}, acc3 = {0.f, 0.f};
    #pragma unroll
    for (int k = 0; k < HIDC; k += 4) {
        float4 a0 = *(const float4*)(xp + k);
        float4 a1 = *(const float4*)(xp + HIDC + k);
        float4 a2 = *(const float4*)(xp + 2 * HIDC + k);
        float4 a3 = *(const float4*)(xp + 3 * HIDC + k);
        float2 b0 = *(const float2*)&ws[(k + 0) * OUTC + 2 * lane];
        float2 b1 = *(const float2*)&ws[(k + 1) * OUTC + 2 * lane];
        float2 b2 = *(const float2*)&ws[(k + 2) * OUTC + 2 * lane];
        float2 b3 = *(const float2*)&ws[(k + 3) * OUTC + 2 * lane];
        acc0.x = fmaf(a0.x, b0.x, acc0.x); acc0.y = fmaf(a0.x, b0.y, acc0.y);
        acc0.x = fmaf(a0.y, b1.x, acc0.x); acc0.y = fmaf(a0.y, b1.y, acc0.y);
        acc0.x = fmaf(a0.z, b2.x, acc0.x); acc0.y = fmaf(a0.z, b2.y, acc0.y);
        acc0.x = fmaf(a0.w, b3.x, acc0.x); acc0.y = fmaf(a0.w, b3.y, acc0.y);
        acc1.x = fmaf(a1.x, b0.x, acc1.x); acc1.y = fmaf(a1.x, b0.y, acc1.y);
        acc1.x = fmaf(a1.y, b1.x, acc1.x); acc1.y = fmaf(a1.y, b1.y, acc1.y);
        acc1.x = fmaf(a1.z, b2.x, acc1.x); acc1.y = fmaf(a1.z, b2.y, acc1.y);
        acc1.x = fmaf(a1.w, b3.x, acc1.x); acc1.y = fmaf(a1.w, b3.y, acc1.y);
        acc2.x = fmaf(a2.x, b0.x, acc2.x); acc2.y = fmaf(a2.x, b0.y, acc2.y);
        acc2.x = fmaf(a2.y, b1.x, acc2.x); acc2.y = fmaf(a2.y, b1.y, acc2.y);
        acc2.x = fmaf(a2.z, b2.x, acc2.x); acc2.y = fmaf(a2.z, b2.y, acc2.y);
        acc2.x = fmaf(a2.w, b3.x, acc2.x); acc2.y = fmaf(a2.w, b3.y, acc2.y);
        acc3.x = fmaf(a3.x, b0.x, acc3.x); acc3.y = fmaf(a3.x, b0.y, acc3.y);
        acc3.x = fmaf(a3.y, b1.x, acc3.x); acc3.y = fmaf(a3.y, b1.y, acc3.y);
        acc3.x = fmaf(a3.z, b2.x, acc3.x); acc3.y = fmaf(a3.z, b2.y, acc3.y);
        acc3.x = fmaf(a3.w, b3.x, acc3.x); acc3.y = fmaf(a3.w, b3.y, acc3.y);
    }
    int row = row0 + wp * 4;
    float d0 = g_dinv[row], d1 = g_dinv[row + 1], d2 = g_dinv[row + 2], d3 = g_dinv[row + 3];
    float2 o;
    o.x = acc0.x * d0; o.y = acc0.y * d0; *(float2*)&g_h2[(row + 0) * OUTC + 2 * lane] = o;
    o.x = acc1.x * d1; o.y = acc1.y * d1; *(float2*)&g_h2[(row + 1) * OUTC + 2 * lane] = o;
    o.x = acc2.x * d2; o.y = acc2.y * d2; *(float2*)&g_h2[(row + 2) * OUTC + 2 * lane] = o;
    o.x = acc3.x * d3; o.y = acc3.y * d3; *(float2*)&g_h2[(row + 3) * OUTC + 2 * lane] = o;
}

// ---------------- 7: aggregation layer 2 + bias + log_softmax ----------------
// warp per node, 2 cols/thread (64 cols).
__global__ void k_agg2(const float* __restrict__ b2, float* __restrict__ out) {
    int node = blockIdx.x * 8 + (threadIdx.x >> 5);
    int lane = threadIdx.x & 31;
    int s = g_rowptr[node], e = g_rowptr[node + 1];
    float ax = 0.f, ay = 0.f;
    int i = s;
    for (; i + 2 <= e; i += 2) {
        int i0 = g_csr[i], i1 = g_csr[i + 1];
        float2 v0 = *(const float2*)&g_h2[i0 * OUTC + 2 * lane];
        float2 v1 = *(const float2*)&g_h2[i1 * OUTC + 2 * lane];
        ax += v0.x + v1.x;
        ay += v0.y + v1.y;
    }
    if (i < e) {
        float2 v = *(const float2*)&g_h2[g_csr[i] * OUTC + 2 * lane];
        ax += v.x; ay += v.y;
    }
    float dv = g_dinv[node];
    float2 bb = *(const float2*)&b2[2 * lane];
    float vx = fmaf(dv, ax, bb.x);
    float vy = fmaf(dv, ay, bb.y);

    float m = fmaxf(vx, vy);
    #pragma unroll
    for (int o = 16; o > 0; o >>= 1) m = fmaxf(m, __shfl_xor_sync(0xffffffffu, m, o));
    float smv = expf(vx - m) + expf(vy - m);
    #pragma unroll
    for (int o = 16; o > 0; o >>= 1) smv += __shfl_xor_sync(0xffffffffu, smv, o);
    float lse = m + logf(smv);
    float2 r = make_float2(vx - lse, vy - lse);
    *(float2*)&out[(size_t)node * OUTC + 2 * lane] = r;
}

// ---------------- launch ----------------
extern "C" void kernel_launch(void* const* d_in, const int* in_sizes, int n_in,
                              void* d_out, int out_size) {
    const float* x  = (const float*)d_in[0];
    const int*   ei = (const int*)d_in[1];     // int32 edge_index (JAX x64 off); probed at runtime
    const float* w1 = (const float*)d_in[2];
    const float* b1 = (const float*)d_in[3];
    const float* w2 = (const float*)d_in[4];
    const float* b2 = (const float*)d_in[5];
    float* out = (float*)d_out;

    k_detect<<<1, 256>>>(ei);
    k_zero<<<NPAD / 256, 256>>>();
    k_cast<<<EE / 256, 256>>>(ei);
    k_scan1<<<NPAD / 4096, 512>>>();
    k_scan2<<<1, 32>>>();
    k_scan3<<<(NN + 255) / 256, 256>>>();
    k_scatter<<<EE / 256, 256>>>();
    k_gemm1<<<NN / 16, 256>>>(x, w1);
    k_agg1<<<NN / 8, 256>>>(b1);
    k_gemm2<<<NN / 32, 256>>>(w2);
    k_agg2<<<NN / 8, 256>>>(b2, out);
}